// round 6
// baseline (speedup 1.0000x reference)
#include <cuda_runtime.h>

#define HH 96
#define WW 96
#define HW 9216
#define NE 64
#define ND 128
#define NK 4
#define NB 2

typedef unsigned long long ull;

// scratch — pixel-major [img][pix][e] layouts
__device__ float g_queries[NB * HW * NE];
__device__ float g_keys[NK * NB * HW * NE];
__device__ float g_values[NB * HW * NE];
__device__ float g_ctxT[NK * NB * HW * NE];
__device__ float g_wattnT2[5 * 32 * NE * 2];  // [phase][ipair][o][2]

__device__ __forceinline__ ull fma2(ull a, ull b, ull c) {
    ull d;
    asm("fma.rn.f32x2 %0, %1, %2, %3;" : "=l"(d) : "l"(a), "l"(b), "l"(c));
    return d;
}
__device__ __forceinline__ ull pack2(float x, float y) {
    ull r; asm("mov.b64 %0, {%1, %2};" : "=l"(r) : "f"(x), "f"(y)); return r;
}
__device__ __forceinline__ float2 unpack2(ull v) {
    float lo, hi; asm("mov.b64 {%0, %1}, %2;" : "=f"(lo), "=f"(hi) : "l"(v));
    return make_float2(lo, hi);
}
__device__ __forceinline__ float tanh_fast(float x) {
    float y; asm("tanh.approx.f32 %0, %1;" : "=f"(y) : "f"(x)); return y;
}

// ============================================================
// ONE producer kernel: blocks [0,288) conv3x3+queries,
// [288,864) keys 1x1 + ctx transpose, [864,944) w_attn repack.
// ============================================================
__global__ void __launch_bounds__(256) producer_kernel(
    const float* __restrict__ decoded,   // [B][128][H][W]
    const float* __restrict__ wv,        // [64][128][3][3]
    const float* __restrict__ bias_v,
    const float* __restrict__ wd,        // [64][128]
    const float* __restrict__ bias_q,
    const float* __restrict__ contexts,  // [K][B][64][H][W]
    const float* __restrict__ we,        // [64][64]
    const float* __restrict__ bias_k,
    const float* __restrict__ wa,        // [64][320]
    float* __restrict__ outq, float* __restrict__ outk,
    float* __restrict__ outv, float* __restrict__ outc)
{
    __shared__ __align__(16) float smu[12160];  // 48.6 KB
    int bid = blockIdx.x;
    int tid = threadIdx.x, lane = tid & 31, cg = tid >> 5;

    if (bid < 288) {
        // ---------- conv3x3 (values) + fused queries ----------
        float* xs = smu;            // [16][120] stride 12
        float* ws = smu + 1920;     // [16*9][64] indexed [l][o], l=ci*9+tap
        float* wq = smu + 11136;    // [16][64]
        int b = bid / 144; int t = bid % 144;
        int yo = (t / 12) * 8, xo = (t % 12) * 8;
        int prow = lane >> 2, pcol0 = (lane & 3) * 2;
        const float* xb = decoded + (size_t)b * ND * HW;
        int wo = tid >> 2, wt4 = tid & 3;

        ull accv[4][2], accq[4][2];
#pragma unroll
        for (int ep = 0; ep < 4; ep++) {
            accv[ep][0] = accv[ep][1] = 0ull;
            accq[ep][0] = accq[ep][1] = 0ull;
        }

        for (int c0 = 0; c0 < ND; c0 += 16) {
            for (int lin = tid; lin < 1600; lin += 256) {
                int hc = lin % 10; int tt = lin / 10; int hr = tt % 10; int ci = tt / 10;
                int gy = yo - 1 + hr, gx = xo - 1 + hc;
                float v = 0.f;
                if ((unsigned)gy < HH && (unsigned)gx < WW)
                    v = xb[(size_t)(c0 + ci) * HW + gy * WW + gx];
                xs[ci * 120 + hr * 12 + hc] = v;
            }
            // stage conv weights: [o][ci][tap] -> ws[l][o]
            {
                const float4* src = (const float4*)(wv + (size_t)wo * (ND * 9) + c0 * 9);
#pragma unroll
                for (int i = 0; i < 9; i++) {
                    float4 v4 = src[wt4 * 9 + i];
                    int l = (wt4 * 9 + i) * 4;
                    ws[l * 64 + wo] = v4.x;
                    ws[(l + 1) * 64 + wo] = v4.y;
                    ws[(l + 2) * 64 + wo] = v4.z;
                    ws[(l + 3) * 64 + wo] = v4.w;
                }
                float4 q4 = *(const float4*)(wd + (size_t)wo * ND + c0 + wt4 * 4);
                wq[(wt4 * 4) * 64 + wo] = q4.x;
                wq[(wt4 * 4 + 1) * 64 + wo] = q4.y;
                wq[(wt4 * 4 + 2) * 64 + wo] = q4.z;
                wq[(wt4 * 4 + 3) * 64 + wo] = q4.w;
            }
            __syncthreads();
#pragma unroll
            for (int ci = 0; ci < 16; ci++) {
#pragma unroll
                for (int dr = 0; dr < 3; dr++) {
                    int rb = ci * 120 + (prow + dr) * 12 + pcol0;
                    float2 xA = *(const float2*)&xs[rb];
                    float2 xB = *(const float2*)&xs[rb + 2];
                    float x0 = xA.x, x1 = xA.y, x2 = xB.x, x3 = xB.y;
                    ull sx[4] = {pack2(x0, x0), pack2(x1, x1),
                                 pack2(x2, x2), pack2(x3, x3)};
#pragma unroll
                    for (int dc = 0; dc < 3; dc++) {
                        const float* wp = ws + (ci * 9 + dr * 3 + dc) * 64 + cg * 8;
                        ulonglong2 wA = *(const ulonglong2*)wp;
                        ulonglong2 wB = *(const ulonglong2*)(wp + 4);
                        accv[0][0] = fma2(wA.x, sx[dc], accv[0][0]);
                        accv[0][1] = fma2(wA.x, sx[dc + 1], accv[0][1]);
                        accv[1][0] = fma2(wA.y, sx[dc], accv[1][0]);
                        accv[1][1] = fma2(wA.y, sx[dc + 1], accv[1][1]);
                        accv[2][0] = fma2(wB.x, sx[dc], accv[2][0]);
                        accv[2][1] = fma2(wB.x, sx[dc + 1], accv[2][1]);
                        accv[3][0] = fma2(wB.y, sx[dc], accv[3][0]);
                        accv[3][1] = fma2(wB.y, sx[dc + 1], accv[3][1]);
                    }
                    if (dr == 1) {
                        const float* qp = wq + ci * 64 + cg * 8;
                        ulonglong2 qa = *(const ulonglong2*)qp;
                        ulonglong2 qb = *(const ulonglong2*)(qp + 4);
                        accq[0][0] = fma2(qa.x, sx[1], accq[0][0]);
                        accq[0][1] = fma2(qa.x, sx[2], accq[0][1]);
                        accq[1][0] = fma2(qa.y, sx[1], accq[1][0]);
                        accq[1][1] = fma2(qa.y, sx[2], accq[1][1]);
                        accq[2][0] = fma2(qb.x, sx[1], accq[2][0]);
                        accq[2][1] = fma2(qb.x, sx[2], accq[2][1]);
                        accq[3][0] = fma2(qb.y, sx[1], accq[3][0]);
                        accq[3][1] = fma2(qb.y, sx[2], accq[3][1]);
                    }
                }
            }
            __syncthreads();
        }
        float4 bva = *(const float4*)&bias_v[cg * 8];
        float4 bvb = *(const float4*)&bias_v[cg * 8 + 4];
        float4 bqa = *(const float4*)&bias_q[cg * 8];
        float4 bqb = *(const float4*)&bias_q[cg * 8 + 4];
        int gp0 = (yo + prow) * WW + xo + pcol0;
#pragma unroll
        for (int pxi = 0; pxi < 2; pxi++) {
            float2 u0 = unpack2(accv[0][pxi]), u1 = unpack2(accv[1][pxi]);
            float2 u2 = unpack2(accv[2][pxi]), u3 = unpack2(accv[3][pxi]);
            float* dv = &outv[((size_t)b * HW + gp0 + pxi) * NE + cg * 8];
            *(float4*)dv = make_float4(u0.x + bva.x, u0.y + bva.y, u1.x + bva.z, u1.y + bva.w);
            *(float4*)(dv + 4) = make_float4(u2.x + bvb.x, u2.y + bvb.y, u3.x + bvb.z, u3.y + bvb.w);
            float2 q0 = unpack2(accq[0][pxi]), q1 = unpack2(accq[1][pxi]);
            float2 q2 = unpack2(accq[2][pxi]), q3 = unpack2(accq[3][pxi]);
            float* dq = &outq[((size_t)b * HW + gp0 + pxi) * NE + cg * 8];
            *(float4*)dq = make_float4(q0.x + bqa.x, q0.y + bqa.y, q1.x + bqa.z, q1.y + bqa.w);
            *(float4*)(dq + 4) = make_float4(q2.x + bqb.x, q2.y + bqb.y, q3.x + bqb.z, q3.y + bqb.w);
        }
    } else if (bid < 864) {
        // ---------- keys 1x1 conv + ctx transpose ----------
        float* xs = smu;          // [16][128]
        float* ws = smu + 2048;   // [16][64]
        int kb = bid - 288;
        int img = kb / 72;
        int p0 = (kb % 72) * 128;
        const float* xb = contexts + (size_t)img * NE * HW + p0;
        int wo = tid >> 2, wt4 = tid & 3;
        int tpx = tid >> 1, thalf = tid & 1;

        ull acc2[4][4];
#pragma unroll
        for (int ep = 0; ep < 4; ep++)
#pragma unroll
            for (int px = 0; px < 4; px++) acc2[ep][px] = 0ull;

        for (int c0 = 0; c0 < NE; c0 += 16) {
#pragma unroll
            for (int rep = 0; rep < 2; rep++) {
                int lin = tid + rep * 256;
                int ci = lin >> 5, px4 = (lin & 31) * 4;
                *(float4*)&xs[ci * 128 + px4] =
                    *(const float4*)&xb[(size_t)(c0 + ci) * HW + px4];
            }
            {
                float4 w4 = *(const float4*)(we + (size_t)wo * NE + c0 + wt4 * 4);
                ws[(wt4 * 4) * 64 + wo] = w4.x;
                ws[(wt4 * 4 + 1) * 64 + wo] = w4.y;
                ws[(wt4 * 4 + 2) * 64 + wo] = w4.z;
                ws[(wt4 * 4 + 3) * 64 + wo] = w4.w;
            }
            __syncthreads();
            // ctx transpose chunk -> [pix][e]
            {
                float v[8];
#pragma unroll
                for (int t = 0; t < 8; t++) v[t] = xs[(thalf * 8 + t) * 128 + tpx];
                float* cd = &outc[((size_t)img * HW + p0 + tpx) * NE + c0 + thalf * 8];
                *(float4*)cd = make_float4(v[0], v[1], v[2], v[3]);
                *(float4*)(cd + 4) = make_float4(v[4], v[5], v[6], v[7]);
            }
#pragma unroll
            for (int ci = 0; ci < 16; ci++) {
                float4 xv = *(float4*)&xs[ci * 128 + lane * 4];
                ull sx[4] = {pack2(xv.x, xv.x), pack2(xv.y, xv.y),
                             pack2(xv.z, xv.z), pack2(xv.w, xv.w)};
                ulonglong2 wA = *(const ulonglong2*)&ws[ci * 64 + cg * 8];
                ulonglong2 wB = *(const ulonglong2*)&ws[ci * 64 + cg * 8 + 4];
#pragma unroll
                for (int px = 0; px < 4; px++) {
                    acc2[0][px] = fma2(wA.x, sx[px], acc2[0][px]);
                    acc2[1][px] = fma2(wA.y, sx[px], acc2[1][px]);
                    acc2[2][px] = fma2(wB.x, sx[px], acc2[2][px]);
                    acc2[3][px] = fma2(wB.y, sx[px], acc2[3][px]);
                }
            }
            __syncthreads();
        }
        float4 ba = *(const float4*)&bias_k[cg * 8];
        float4 bb = *(const float4*)&bias_k[cg * 8 + 4];
#pragma unroll
        for (int px = 0; px < 4; px++) {
            float2 u0 = unpack2(acc2[0][px]), u1 = unpack2(acc2[1][px]);
            float2 u2 = unpack2(acc2[2][px]), u3 = unpack2(acc2[3][px]);
            float* dst = &outk[((size_t)img * HW + p0 + lane * 4 + px) * NE + cg * 8];
            *(float4*)dst = make_float4(u0.x + ba.x, u0.y + ba.y, u1.x + ba.z, u1.y + ba.w);
            *(float4*)(dst + 4) = make_float4(u2.x + bb.x, u2.y + bb.y, u3.x + bb.z, u3.y + bb.w);
        }
    } else {
        // ---------- w_attn repack ----------
        int r = (bid - 864) * 256 + tid;  // < 20480
        int half = r & 1; int r2 = r >> 1;
        int o = r2 & 63; int t = r2 >> 6; int ip = t & 31; int k = t >> 5;
        g_wattnT2[r] = wa[o * 320 + k * 64 + 2 * ip + half];
    }
}

// ============================================================
// Fused attention + output projection.
// ============================================================
__device__ __forceinline__ void final_accum(
    const float* __restrict__ cat, const ull* __restrict__ wsl2,
    int lane, int wr, ull acc0[8], ull acc1[8])
{
#pragma unroll
    for (int it = 0; it < 8; it++) {
        ull w0[4], w1[4];
#pragma unroll
        for (int t = 0; t < 4; t++) {
            int ip = it * 4 + t;
            w0[t] = wsl2[ip * 66 + lane];
            w1[t] = wsl2[ip * 66 + 32 + lane];
        }
#pragma unroll
        for (int j = 0; j < 8; j++) {
            const ull* cp = (const ull*)&cat[(wr * 8 + j) * 68 + it * 8];
            ulonglong2 cA = *(const ulonglong2*)cp;
            ulonglong2 cB = *(const ulonglong2*)(cp + 2);
            ull a0 = acc0[j];
            a0 = fma2(w0[0], cA.x, a0); a0 = fma2(w0[1], cA.y, a0);
            a0 = fma2(w0[2], cB.x, a0); a0 = fma2(w0[3], cB.y, a0);
            acc0[j] = a0;
            ull a1 = acc1[j];
            a1 = fma2(w1[0], cA.x, a1); a1 = fma2(w1[1], cA.y, a1);
            a1 = fma2(w1[2], cB.x, a1); a1 = fma2(w1[3], cB.y, a1);
            acc1[j] = a1;
        }
    }
}

__global__ void __launch_bounds__(256, 2) attn_kernel(
    const float* __restrict__ w_agg,
    const float* __restrict__ b_agg_p,
    const float* __restrict__ b_attn,
    float* __restrict__ out)
{
    extern __shared__ __align__(16) float sm[];
    float* ks  = sm;                    // [100][68]
    float* cs  = ks + 100 * 68;         // [100][68]
    float* cat = cs + 100 * 68;         // [64][68]
    ull* wsl2  = (ull*)(cat + 64 * 68); // [32][66]

    int tid = threadIdx.x, lane = tid & 31, wr = tid >> 5;
    int b = blockIdx.z, yo = blockIdx.y * 8, xo = blockIdx.x * 8;
    int j = lane >> 2, eq = lane & 3;
    int pix = wr * 8 + j;
    float bagg = b_agg_p[0];

    {
        const float* vb = g_values + (size_t)b * HW * NE;
        for (int lin = tid; lin < 1024; lin += 256) {
            int p = lin >> 4, e4 = (lin & 15) * 4;
            int gp = (yo + (p >> 3)) * WW + xo + (p & 7);
            *(float4*)&cat[p * 68 + e4] = *(const float4*)&vb[(size_t)gp * NE + e4];
        }
        const ulonglong2* wsrc = (const ulonglong2*)g_wattnT2;
        for (int lin = tid; lin < 1024; lin += 256) {
            ulonglong2 u = wsrc[lin];
            int o2 = (lin & 31) * 2, ip = lin >> 5;
            *(ulonglong2*)&wsl2[ip * 66 + o2] = u;
        }
    }

    float qreg[16], waggr[16];
    {
        const float* qb = g_queries +
            ((size_t)b * HW + (yo + wr) * WW + xo + j) * NE + eq * 16;
#pragma unroll
        for (int u = 0; u < 4; u++) {
            float4 qv = *(const float4*)(qb + u * 4);
            qreg[u*4] = qv.x; qreg[u*4+1] = qv.y; qreg[u*4+2] = qv.z; qreg[u*4+3] = qv.w;
            float4 wv = *(const float4*)&w_agg[eq * 16 + u * 4];
            waggr[u*4] = wv.x; waggr[u*4+1] = wv.y; waggr[u*4+2] = wv.z; waggr[u*4+3] = wv.w;
        }
    }
    __syncthreads();

    ull acc0[8], acc1[8];
#pragma unroll
    for (int t = 0; t < 8; t++) { acc0[t] = 0ull; acc1[t] = 0ull; }
    final_accum(cat, wsl2, lane, wr, acc0, acc1);

    for (int k = 0; k < NK; k++) {
        __syncthreads();
        const float* kb = g_keys + (size_t)(k * NB + b) * HW * NE;
        const float* cb = g_ctxT + (size_t)(k * NB + b) * HW * NE;
        for (int lin = tid; lin < 1600; lin += 256) {
            int hp = lin >> 4, e4 = (lin & 15) * 4;
            int hr = hp / 10, hc = hp % 10;
            int gy = yo - 1 + hr, gx = xo - 1 + hc;
            float4 kv = make_float4(0.f, 0.f, 0.f, 0.f), cv = kv;
            if ((unsigned)gy < HH && (unsigned)gx < WW) {
                size_t off = ((size_t)gy * WW + gx) * NE + e4;
                kv = *(const float4*)&kb[off];
                cv = *(const float4*)&cb[off];
            }
            *(float4*)&ks[hp * 68 + e4] = kv;
            *(float4*)&cs[hp * 68 + e4] = cv;
        }
        const ulonglong2* wsrc = (const ulonglong2*)g_wattnT2 + (k + 1) * 1024;
        for (int lin = tid; lin < 1024; lin += 256) {
            ulonglong2 u = wsrc[lin];
            int o2 = (lin & 31) * 2, ip = lin >> 5;
            *(ulonglong2*)&wsl2[ip * 66 + o2] = u;
        }
        __syncthreads();

        int base_hp = wr * 10 + j;
        float s[9];
#pragma unroll
        for (int n = 0; n < 9; n++) {
            const int dr = n / 3, dc = n % 3;
            const float* kp = &ks[(base_hp + dr * 10 + dc) * 68 + eq * 16];
            float pa = 0.f, pb = 0.f;
#pragma unroll
            for (int u = 0; u < 2; u++) {
                float4 k0 = *(const float4*)(kp + u * 8);
                float4 k1 = *(const float4*)(kp + u * 8 + 4);
                pa = fmaf(waggr[u*8+0], tanh_fast(qreg[u*8+0] + k0.x), pa);
                pb = fmaf(waggr[u*8+1], tanh_fast(qreg[u*8+1] + k0.y), pb);
                pa = fmaf(waggr[u*8+2], tanh_fast(qreg[u*8+2] + k0.z), pa);
                pb = fmaf(waggr[u*8+3], tanh_fast(qreg[u*8+3] + k0.w), pb);
                pa = fmaf(waggr[u*8+4], tanh_fast(qreg[u*8+4] + k1.x), pa);
                pb = fmaf(waggr[u*8+5], tanh_fast(qreg[u*8+5] + k1.y), pb);
                pa = fmaf(waggr[u*8+6], tanh_fast(qreg[u*8+6] + k1.z), pa);
                pb = fmaf(waggr[u*8+7], tanh_fast(qreg[u*8+7] + k1.w), pb);
            }
            float part = pa + pb;
            part += __shfl_xor_sync(0xffffffffu, part, 1);
            part += __shfl_xor_sync(0xffffffffu, part, 2);
            bool valid = ((unsigned)(yo + wr + dr - 1) < HH) &&
                         ((unsigned)(xo + j + dc - 1) < WW);
            s[n] = valid ? part + bagg : -1e30f;
        }
        float m = s[0];
#pragma unroll
        for (int n = 1; n < 9; n++) m = fmaxf(m, s[n]);
        float p[9], ps = 0.f;
#pragma unroll
        for (int n = 0; n < 9; n++) { p[n] = __expf(s[n] - m); ps += p[n]; }
        float rinv = __fdividef(1.f, ps);

        ull a2[8];
#pragma unroll
        for (int t = 0; t < 8; t++) a2[t] = 0ull;
#pragma unroll
        for (int n = 0; n < 9; n++) {
            const int dr = n / 3, dc = n % 3;
            float pn = p[n] * rinv;
            ull pr = pack2(pn, pn);
            const float* cp = &cs[(base_hp + dr * 10 + dc) * 68 + eq * 16];
            ulonglong2 cA = *(const ulonglong2*)cp;
            ulonglong2 cB = *(const ulonglong2*)(cp + 4);
            ulonglong2 cC = *(const ulonglong2*)(cp + 8);
            ulonglong2 cD = *(const ulonglong2*)(cp + 12);
            a2[0] = fma2(pr, cA.x, a2[0]); a2[1] = fma2(pr, cA.y, a2[1]);
            a2[2] = fma2(pr, cB.x, a2[2]); a2[3] = fma2(pr, cB.y, a2[3]);
            a2[4] = fma2(pr, cC.x, a2[4]); a2[5] = fma2(pr, cC.y, a2[5]);
            a2[6] = fma2(pr, cD.x, a2[6]); a2[7] = fma2(pr, cD.y, a2[7]);
        }
        {
            float* dp = &cat[pix * 68 + eq * 16];
            ulonglong2 t0; t0.x = a2[0]; t0.y = a2[1]; *(ulonglong2*)dp = t0;
            ulonglong2 t1; t1.x = a2[2]; t1.y = a2[3]; *(ulonglong2*)(dp + 4) = t1;
            ulonglong2 t2; t2.x = a2[4]; t2.y = a2[5]; *(ulonglong2*)(dp + 8) = t2;
            ulonglong2 t3; t3.x = a2[6]; t3.y = a2[7]; *(ulonglong2*)(dp + 12) = t3;
        }
        __syncwarp();
        final_accum(cat, wsl2, lane, wr, acc0, acc1);
    }

    float ba0 = b_attn[lane], ba1 = b_attn[lane + 32];
    __syncthreads();
#pragma unroll
    for (int t = 0; t < 8; t++) {
        int px = wr * 8 + t;
        float2 z0 = unpack2(acc0[t]);
        float2 z1 = unpack2(acc1[t]);
        float r0 = z0.x + z0.y + ba0; r0 = (r0 >= 0.f) ? r0 : 0.2f * r0;
        float r1 = z1.x + z1.y + ba1; r1 = (r1 >= 0.f) ? r1 : 0.2f * r1;
        cat[px * 68 + lane] = r0;
        cat[px * 68 + 32 + lane] = r1;
    }
    __syncthreads();
    for (int lin = tid; lin < 4096; lin += 256) {
        int col = lin & 7, row = (lin >> 3) & 7, e = lin >> 6;
        out[(b * NE + e) * HW + (yo + row) * WW + xo + col] =
            cat[(row * 8 + col) * 68 + e];
    }
}

// ============================================================
extern "C" void kernel_launch(void* const* d_in, const int* in_sizes, int n_in,
                              void* d_out, int out_size)
{
    (void)in_sizes; (void)n_in; (void)out_size;
    const float* contexts = (const float*)d_in[0];
    const float* decoded  = (const float*)d_in[1];
    const float* w_enc    = (const float*)d_in[2];
    const float* b_enc    = (const float*)d_in[3];
    const float* w_dec    = (const float*)d_in[4];
    const float* b_dec    = (const float*)d_in[5];
    const float* w_agg    = (const float*)d_in[6];
    const float* b_agg    = (const float*)d_in[7];
    const float* w_val    = (const float*)d_in[8];
    const float* b_val    = (const float*)d_in[9];
    const float* w_attn   = (const float*)d_in[10];
    const float* b_attn   = (const float*)d_in[11];
    float* out = (float*)d_out;

    float *gq, *gk, *gv, *gc;
    cudaGetSymbolAddress((void**)&gq, g_queries);
    cudaGetSymbolAddress((void**)&gk, g_keys);
    cudaGetSymbolAddress((void**)&gv, g_values);
    cudaGetSymbolAddress((void**)&gc, g_ctxT);

    producer_kernel<<<944, 256>>>(
        decoded, w_val, b_val, w_dec, b_dec,
        contexts, w_enc, b_enc, w_attn,
        gq, gk, gv, gc);

    const int SMEM_ATTN = (100 * 68 + 100 * 68 + 64 * 68 + 32 * 66 * 2) * 4;
    cudaFuncSetAttribute(attn_kernel,
                         cudaFuncAttributeMaxDynamicSharedMemorySize, SMEM_ATTN);
    attn_kernel<<<dim3(12, 12, NB), 256, SMEM_ATTN>>>(
        w_agg, b_agg, b_attn, out);
}

// round 7
// speedup vs baseline: 1.1449x; 1.1449x over previous
#include <cuda_runtime.h>

#define HH 96
#define WW 96
#define HW 9216
#define NE 64
#define ND 128
#define NK 4
#define NB 2
#define NCTA 296

typedef unsigned long long ull;

// scratch — pixel-major [img][pix][e] layouts
__device__ float g_queries[NB * HW * NE];
__device__ float g_keys[NK * NB * HW * NE];
__device__ float g_values[NB * HW * NE];
__device__ float g_ctxT[NK * NB * HW * NE];
__device__ float g_wpack[ND * 9 * NE];        // [ci][tap][o]
__device__ float g_wdecT[ND * NE];            // [ci][o]
__device__ float g_wencT[NE * NE];            // [ci][o]
__device__ float g_wattnT2[5 * 32 * NE * 2];  // [phase][ipair][o][2]
__device__ unsigned g_bar;

__device__ __forceinline__ ull fma2(ull a, ull b, ull c) {
    ull d;
    asm("fma.rn.f32x2 %0, %1, %2, %3;" : "=l"(d) : "l"(a), "l"(b), "l"(c));
    return d;
}
__device__ __forceinline__ ull pack2(float x, float y) {
    ull r; asm("mov.b64 %0, {%1, %2};" : "=l"(r) : "f"(x), "f"(y)); return r;
}
__device__ __forceinline__ float2 unpack2(ull v) {
    float lo, hi; asm("mov.b64 {%0, %1}, %2;" : "=f"(lo), "=f"(hi) : "l"(v));
    return make_float2(lo, hi);
}
__device__ __forceinline__ float tanh_fast(float x) {
    float y; asm("tanh.approx.f32 %0, %1;" : "=f"(y) : "f"(x)); return y;
}

// ============================================================
// repack: weight layouts + barrier reset (runs before mega).
// ============================================================
__global__ void __launch_bounds__(256) repack_kernel(
    const float* __restrict__ wv, const float* __restrict__ wd,
    const float* __restrict__ we, const float* __restrict__ wa)
{
    int i = blockIdx.x * 256 + threadIdx.x;
    if (i == 0) g_bar = 0u;
    if (i < 73728) {
        int o = i & 63; int t = i >> 6; int tap = t % 9; int ci = t / 9;
        g_wpack[i] = wv[(size_t)o * (ND * 9) + ci * 9 + tap];
    } else if (i < 81920) {
        int r = i - 73728; int o = r & 63; int ci = r >> 6;
        g_wdecT[r] = wd[o * ND + ci];
    } else if (i < 86016) {
        int r = i - 81920; int o = r & 63; int ci = r >> 6;
        g_wencT[r] = we[o * NE + ci];
    } else if (i < 106496) {
        int r = i - 86016;
        int half = r & 1; int r2 = r >> 1;
        int o = r2 & 63; int t = r2 >> 6; int ip = t & 31; int k = t >> 5;
        g_wattnT2[r] = wa[o * 320 + k * 64 + 2 * ip + half];
    }
}

// ============================================================
__device__ __forceinline__ void final_accum(
    const float* __restrict__ cat, const ull* __restrict__ wsl2,
    int lane, int wr, ull acc0[8], ull acc1[8])
{
#pragma unroll
    for (int it = 0; it < 8; it++) {
        ull w0[4], w1[4];
#pragma unroll
        for (int t = 0; t < 4; t++) {
            int ip = it * 4 + t;
            w0[t] = wsl2[ip * 66 + lane];
            w1[t] = wsl2[ip * 66 + 32 + lane];
        }
#pragma unroll
        for (int j = 0; j < 8; j++) {
            const ull* cp = (const ull*)&cat[(wr * 8 + j) * 68 + it * 8];
            ulonglong2 cA = *(const ulonglong2*)cp;
            ulonglong2 cB = *(const ulonglong2*)(cp + 2);
            ull a0 = acc0[j];
            a0 = fma2(w0[0], cA.x, a0); a0 = fma2(w0[1], cA.y, a0);
            a0 = fma2(w0[2], cB.x, a0); a0 = fma2(w0[3], cB.y, a0);
            acc0[j] = a0;
            ull a1 = acc1[j];
            a1 = fma2(w1[0], cA.x, a1); a1 = fma2(w1[1], cA.y, a1);
            a1 = fma2(w1[2], cB.x, a1); a1 = fma2(w1[3], cB.y, a1);
            acc1[j] = a1;
        }
    }
}

// ============================================================
// MEGA kernel: conv+queries, keys+ctxT, global barrier, attn.
// grid = 296 = 2 CTAs x 148 SMs (all resident; spin-safe).
// ============================================================
__global__ void __launch_bounds__(256, 2) mega_kernel(
    const float* __restrict__ decoded,
    const float* __restrict__ bias_v,
    const float* __restrict__ bias_q,
    const float* __restrict__ contexts,
    const float* __restrict__ bias_k,
    const float* __restrict__ w_agg,
    const float* __restrict__ b_agg_p,
    const float* __restrict__ b_attn,
    float* __restrict__ out)
{
    extern __shared__ __align__(16) float sm[];
    int c = blockIdx.x;
    int tid = threadIdx.x, lane = tid & 31, cg = tid >> 5;

    // ================= phase 1: conv3x3 (values) + queries =================
    if (c < 288) {
        float* xs = sm;             // [16][112]
        float* ws = sm + 1792;      // [16*9][64]
        float* wq = sm + 11008;     // [16][64]
        int b = c / 144; int t = c % 144;
        int yo = (t / 12) * 8, xo = (t % 12) * 8;
        int prow = lane >> 2, pcol0 = (lane & 3) * 2;
        const float* xb = decoded + (size_t)b * ND * HW;

        ull accv[4][2], accq[4][2];
#pragma unroll
        for (int ep = 0; ep < 4; ep++) {
            accv[ep][0] = accv[ep][1] = 0ull;
            accq[ep][0] = accq[ep][1] = 0ull;
        }
        for (int c0 = 0; c0 < ND; c0 += 16) {
            for (int lin = tid; lin < 1600; lin += 256) {
                int hc = lin % 10; int tt = lin / 10; int hr = tt % 10; int ci = tt / 10;
                int gy = yo - 1 + hr, gx = xo - 1 + hc;
                float v = 0.f;
                if ((unsigned)gy < HH && (unsigned)gx < WW)
                    v = xb[(size_t)(c0 + ci) * HW + gy * WW + gx];
                xs[ci * 112 + hr * 11 + hc] = v;
            }
#pragma unroll
            for (int r = 0; r < 9; r++)
                ((float4*)ws)[tid + r * 256] =
                    ((const float4*)(g_wpack + c0 * 576))[tid + r * 256];
            ((float4*)wq)[tid] = ((const float4*)(g_wdecT + c0 * 64))[tid];
            __syncthreads();
#pragma unroll
            for (int ci = 0; ci < 16; ci++) {
#pragma unroll
                for (int dr = 0; dr < 3; dr++) {
                    int rb = ci * 112 + (prow + dr) * 11 + pcol0;
                    float x0 = xs[rb], x1 = xs[rb + 1];
                    float x2 = xs[rb + 2], x3 = xs[rb + 3];
                    ull sx[4] = {pack2(x0, x0), pack2(x1, x1),
                                 pack2(x2, x2), pack2(x3, x3)};
#pragma unroll
                    for (int dc = 0; dc < 3; dc++) {
                        const float* wp = ws + (ci * 9 + dr * 3 + dc) * 64 + cg * 8;
                        ulonglong2 wA = *(const ulonglong2*)wp;
                        ulonglong2 wB = *(const ulonglong2*)(wp + 4);
                        accv[0][0] = fma2(wA.x, sx[dc], accv[0][0]);
                        accv[0][1] = fma2(wA.x, sx[dc + 1], accv[0][1]);
                        accv[1][0] = fma2(wA.y, sx[dc], accv[1][0]);
                        accv[1][1] = fma2(wA.y, sx[dc + 1], accv[1][1]);
                        accv[2][0] = fma2(wB.x, sx[dc], accv[2][0]);
                        accv[2][1] = fma2(wB.x, sx[dc + 1], accv[2][1]);
                        accv[3][0] = fma2(wB.y, sx[dc], accv[3][0]);
                        accv[3][1] = fma2(wB.y, sx[dc + 1], accv[3][1]);
                    }
                    if (dr == 1) {
                        const float* qp = wq + ci * 64 + cg * 8;
                        ulonglong2 qa = *(const ulonglong2*)qp;
                        ulonglong2 qb = *(const ulonglong2*)(qp + 4);
                        accq[0][0] = fma2(qa.x, sx[1], accq[0][0]);
                        accq[0][1] = fma2(qa.x, sx[2], accq[0][1]);
                        accq[1][0] = fma2(qa.y, sx[1], accq[1][0]);
                        accq[1][1] = fma2(qa.y, sx[2], accq[1][1]);
                        accq[2][0] = fma2(qb.x, sx[1], accq[2][0]);
                        accq[2][1] = fma2(qb.x, sx[2], accq[2][1]);
                        accq[3][0] = fma2(qb.y, sx[1], accq[3][0]);
                        accq[3][1] = fma2(qb.y, sx[2], accq[3][1]);
                    }
                }
            }
            __syncthreads();
        }
        float4 bva = *(const float4*)&bias_v[cg * 8];
        float4 bvb = *(const float4*)&bias_v[cg * 8 + 4];
        float4 bqa = *(const float4*)&bias_q[cg * 8];
        float4 bqb = *(const float4*)&bias_q[cg * 8 + 4];
        int gp0 = (yo + prow) * WW + xo + pcol0;
#pragma unroll
        for (int pxi = 0; pxi < 2; pxi++) {
            float2 u0 = unpack2(accv[0][pxi]), u1 = unpack2(accv[1][pxi]);
            float2 u2 = unpack2(accv[2][pxi]), u3 = unpack2(accv[3][pxi]);
            float* dv = &g_values[((size_t)b * HW + gp0 + pxi) * NE + cg * 8];
            *(float4*)dv = make_float4(u0.x + bva.x, u0.y + bva.y, u1.x + bva.z, u1.y + bva.w);
            *(float4*)(dv + 4) = make_float4(u2.x + bvb.x, u2.y + bvb.y, u3.x + bvb.z, u3.y + bvb.w);
            float2 q0 = unpack2(accq[0][pxi]), q1 = unpack2(accq[1][pxi]);
            float2 q2 = unpack2(accq[2][pxi]), q3 = unpack2(accq[3][pxi]);
            float* dq = &g_queries[((size_t)b * HW + gp0 + pxi) * NE + cg * 8];
            *(float4*)dq = make_float4(q0.x + bqa.x, q0.y + bqa.y, q1.x + bqa.z, q1.y + bqa.w);
            *(float4*)(dq + 4) = make_float4(q2.x + bqb.x, q2.y + bqb.y, q3.x + bqb.z, q3.y + bqb.w);
        }
    }

    // ================= phase 2: keys 1x1 + ctx transpose =================
#pragma unroll 1
    for (int rep = 0; rep < 2; rep++) {
        int kt = (rep == 0) ? c : NCTA + c;
        if (kt >= 576) break;
        __syncthreads();
        float* xs = sm;           // [16][128]
        float* ws = sm + 2048;    // [16][64]
        int img = kt / 72;
        int p0 = (kt % 72) * 128;
        const float* xb = contexts + (size_t)img * NE * HW + p0;
        int tpx = tid >> 1, thalf = tid & 1;

        ull acc2[4][4];
#pragma unroll
        for (int ep = 0; ep < 4; ep++)
#pragma unroll
            for (int px = 0; px < 4; px++) acc2[ep][px] = 0ull;

        for (int c0 = 0; c0 < NE; c0 += 16) {
#pragma unroll
            for (int rr = 0; rr < 2; rr++) {
                int lin = tid + rr * 256;
                int ci = lin >> 5, px4 = (lin & 31) * 4;
                *(float4*)&xs[ci * 128 + px4] =
                    *(const float4*)&xb[(size_t)(c0 + ci) * HW + px4];
            }
            ((float4*)ws)[tid] = ((const float4*)(g_wencT + c0 * 64))[tid];
            __syncthreads();
            {
                float v[8];
#pragma unroll
                for (int t = 0; t < 8; t++) v[t] = xs[(thalf * 8 + t) * 128 + tpx];
                float* cd = &g_ctxT[((size_t)img * HW + p0 + tpx) * NE + c0 + thalf * 8];
                *(float4*)cd = make_float4(v[0], v[1], v[2], v[3]);
                *(float4*)(cd + 4) = make_float4(v[4], v[5], v[6], v[7]);
            }
#pragma unroll
            for (int ci = 0; ci < 16; ci++) {
                float4 xv = *(float4*)&xs[ci * 128 + lane * 4];
                ull sx[4] = {pack2(xv.x, xv.x), pack2(xv.y, xv.y),
                             pack2(xv.z, xv.z), pack2(xv.w, xv.w)};
                ulonglong2 wA = *(const ulonglong2*)&ws[ci * 64 + cg * 8];
                ulonglong2 wB = *(const ulonglong2*)&ws[ci * 64 + cg * 8 + 4];
#pragma unroll
                for (int px = 0; px < 4; px++) {
                    acc2[0][px] = fma2(wA.x, sx[px], acc2[0][px]);
                    acc2[1][px] = fma2(wA.y, sx[px], acc2[1][px]);
                    acc2[2][px] = fma2(wB.x, sx[px], acc2[2][px]);
                    acc2[3][px] = fma2(wB.y, sx[px], acc2[3][px]);
                }
            }
            __syncthreads();
        }
        float4 ba = *(const float4*)&bias_k[cg * 8];
        float4 bb = *(const float4*)&bias_k[cg * 8 + 4];
#pragma unroll
        for (int px = 0; px < 4; px++) {
            float2 u0 = unpack2(acc2[0][px]), u1 = unpack2(acc2[1][px]);
            float2 u2 = unpack2(acc2[2][px]), u3 = unpack2(acc2[3][px]);
            float* dst = &g_keys[((size_t)img * HW + p0 + lane * 4 + px) * NE + cg * 8];
            *(float4*)dst = make_float4(u0.x + ba.x, u0.y + ba.y, u1.x + ba.z, u1.y + ba.w);
            *(float4*)(dst + 4) = make_float4(u2.x + bb.x, u2.y + bb.y, u3.x + bb.z, u3.y + bb.w);
        }
    }

    // ================= device-wide barrier =================
    __syncthreads();
    if (tid == 0) {
        __threadfence();
        atomicAdd(&g_bar, 1u);
        unsigned v;
        do {
            asm volatile("ld.acquire.gpu.global.u32 %0, [%1];"
                         : "=r"(v) : "l"(&g_bar));
        } while (v < NCTA);
    }
    __syncthreads();

    // ================= phase 3: attention + projection =================
    if (c >= 288) return;
    {
        float* ks  = sm;                    // [100][68]
        float* cs  = ks + 100 * 68;         // [100][68]
        float* cat = cs + 100 * 68;         // [64][68]
        ull* wsl2  = (ull*)(cat + 64 * 68); // [32][66]

        int b = c / 144; int t = c % 144;
        int yo = (t / 12) * 8, xo = (t % 12) * 8;
        int wr = cg;
        int j = lane >> 2, eq = lane & 3;
        int pix = wr * 8 + j;
        float bagg = b_agg_p[0];

        {
            const float* vb = g_values + (size_t)b * HW * NE;
            for (int lin = tid; lin < 1024; lin += 256) {
                int p = lin >> 4, e4 = (lin & 15) * 4;
                int gp = (yo + (p >> 3)) * WW + xo + (p & 7);
                *(float4*)&cat[p * 68 + e4] = *(const float4*)&vb[(size_t)gp * NE + e4];
            }
            const ulonglong2* wsrc = (const ulonglong2*)g_wattnT2;
            for (int lin = tid; lin < 1024; lin += 256) {
                ulonglong2 u = wsrc[lin];
                int o2 = (lin & 31) * 2, ip = lin >> 5;
                *(ulonglong2*)&wsl2[ip * 66 + o2] = u;
            }
        }
        float qreg[16], waggr[16];
        {
            const float* qb = g_queries +
                ((size_t)b * HW + (yo + wr) * WW + xo + j) * NE + eq * 16;
#pragma unroll
            for (int u = 0; u < 4; u++) {
                float4 qv = *(const float4*)(qb + u * 4);
                qreg[u*4] = qv.x; qreg[u*4+1] = qv.y; qreg[u*4+2] = qv.z; qreg[u*4+3] = qv.w;
                float4 wv2 = *(const float4*)&w_agg[eq * 16 + u * 4];
                waggr[u*4] = wv2.x; waggr[u*4+1] = wv2.y; waggr[u*4+2] = wv2.z; waggr[u*4+3] = wv2.w;
            }
        }
        __syncthreads();

        ull acc0[8], acc1[8];
#pragma unroll
        for (int t2 = 0; t2 < 8; t2++) { acc0[t2] = 0ull; acc1[t2] = 0ull; }
        final_accum(cat, wsl2, lane, wr, acc0, acc1);

        for (int k = 0; k < NK; k++) {
            __syncthreads();
            const float* kb = g_keys + (size_t)(k * NB + b) * HW * NE;
            const float* cb = g_ctxT + (size_t)(k * NB + b) * HW * NE;
            for (int lin = tid; lin < 1600; lin += 256) {
                int hp = lin >> 4, e4 = (lin & 15) * 4;
                int hr = hp / 10, hc = hp % 10;
                int gy = yo - 1 + hr, gx = xo - 1 + hc;
                float4 kv = make_float4(0.f, 0.f, 0.f, 0.f), cv = kv;
                if ((unsigned)gy < HH && (unsigned)gx < WW) {
                    size_t off = ((size_t)gy * WW + gx) * NE + e4;
                    kv = *(const float4*)&kb[off];
                    cv = *(const float4*)&cb[off];
                }
                *(float4*)&ks[hp * 68 + e4] = kv;
                *(float4*)&cs[hp * 68 + e4] = cv;
            }
            const ulonglong2* wsrc = (const ulonglong2*)g_wattnT2 + (k + 1) * 1024;
            for (int lin = tid; lin < 1024; lin += 256) {
                ulonglong2 u = wsrc[lin];
                int o2 = (lin & 31) * 2, ip = lin >> 5;
                *(ulonglong2*)&wsl2[ip * 66 + o2] = u;
            }
            __syncthreads();

            int base_hp = wr * 10 + j;
            float s[9];
#pragma unroll
            for (int n = 0; n < 9; n++) {
                const int dr = n / 3, dc = n % 3;
                const float* kp = &ks[(base_hp + dr * 10 + dc) * 68 + eq * 16];
                float pa = 0.f, pb = 0.f;
#pragma unroll
                for (int u = 0; u < 2; u++) {
                    float4 k0 = *(const float4*)(kp + u * 8);
                    float4 k1 = *(const float4*)(kp + u * 8 + 4);
                    pa = fmaf(waggr[u*8+0], tanh_fast(qreg[u*8+0] + k0.x), pa);
                    pb = fmaf(waggr[u*8+1], tanh_fast(qreg[u*8+1] + k0.y), pb);
                    pa = fmaf(waggr[u*8+2], tanh_fast(qreg[u*8+2] + k0.z), pa);
                    pb = fmaf(waggr[u*8+3], tanh_fast(qreg[u*8+3] + k0.w), pb);
                    pa = fmaf(waggr[u*8+4], tanh_fast(qreg[u*8+4] + k1.x), pa);
                    pb = fmaf(waggr[u*8+5], tanh_fast(qreg[u*8+5] + k1.y), pb);
                    pa = fmaf(waggr[u*8+6], tanh_fast(qreg[u*8+6] + k1.z), pa);
                    pb = fmaf(waggr[u*8+7], tanh_fast(qreg[u*8+7] + k1.w), pb);
                }
                float part = pa + pb;
                part += __shfl_xor_sync(0xffffffffu, part, 1);
                part += __shfl_xor_sync(0xffffffffu, part, 2);
                bool valid = ((unsigned)(yo + wr + dr - 1) < HH) &&
                             ((unsigned)(xo + j + dc - 1) < WW);
                s[n] = valid ? part + bagg : -1e30f;
            }
            float m = s[0];
#pragma unroll
            for (int n = 1; n < 9; n++) m = fmaxf(m, s[n]);
            float p[9], ps = 0.f;
#pragma unroll
            for (int n = 0; n < 9; n++) { p[n] = __expf(s[n] - m); ps += p[n]; }
            float rinv = __fdividef(1.f, ps);

            ull a2[8];
#pragma unroll
            for (int t2 = 0; t2 < 8; t2++) a2[t2] = 0ull;
#pragma unroll
            for (int n = 0; n < 9; n++) {
                const int dr = n / 3, dc = n % 3;
                float pn = p[n] * rinv;
                ull pr = pack2(pn, pn);
                const float* cp = &cs[(base_hp + dr * 10 + dc) * 68 + eq * 16];
                ulonglong2 cA = *(const ulonglong2*)cp;
                ulonglong2 cB = *(const ulonglong2*)(cp + 4);
                ulonglong2 cC = *(const ulonglong2*)(cp + 8);
                ulonglong2 cD = *(const ulonglong2*)(cp + 12);
                a2[0] = fma2(pr, cA.x, a2[0]); a2[1] = fma2(pr, cA.y, a2[1]);
                a2[2] = fma2(pr, cB.x, a2[2]); a2[3] = fma2(pr, cB.y, a2[3]);
                a2[4] = fma2(pr, cC.x, a2[4]); a2[5] = fma2(pr, cC.y, a2[5]);
                a2[6] = fma2(pr, cD.x, a2[6]); a2[7] = fma2(pr, cD.y, a2[7]);
            }
            {
                float* dp = &cat[pix * 68 + eq * 16];
                ulonglong2 t0; t0.x = a2[0]; t0.y = a2[1]; *(ulonglong2*)dp = t0;
                ulonglong2 t1; t1.x = a2[2]; t1.y = a2[3]; *(ulonglong2*)(dp + 4) = t1;
                ulonglong2 t2; t2.x = a2[4]; t2.y = a2[5]; *(ulonglong2*)(dp + 8) = t2;
                ulonglong2 t3; t3.x = a2[6]; t3.y = a2[7]; *(ulonglong2*)(dp + 12) = t3;
            }
            __syncwarp();
            final_accum(cat, wsl2, lane, wr, acc0, acc1);
        }

        float ba0 = b_attn[lane], ba1 = b_attn[lane + 32];
        __syncthreads();
#pragma unroll
        for (int t2 = 0; t2 < 8; t2++) {
            int px = wr * 8 + t2;
            float2 z0 = unpack2(acc0[t2]);
            float2 z1 = unpack2(acc1[t2]);
            float r0 = z0.x + z0.y + ba0; r0 = (r0 >= 0.f) ? r0 : 0.2f * r0;
            float r1 = z1.x + z1.y + ba1; r1 = (r1 >= 0.f) ? r1 : 0.2f * r1;
            cat[px * 68 + lane] = r0;
            cat[px * 68 + 32 + lane] = r1;
        }
        __syncthreads();
        for (int lin = tid; lin < 4096; lin += 256) {
            int col = lin & 7, row = (lin >> 3) & 7, e = lin >> 6;
            out[(b * NE + e) * HW + (yo + row) * WW + xo + col] =
                cat[(row * 8 + col) * 68 + e];
        }
    }
}

// ============================================================
extern "C" void kernel_launch(void* const* d_in, const int* in_sizes, int n_in,
                              void* d_out, int out_size)
{
    (void)in_sizes; (void)n_in; (void)out_size;
    const float* contexts = (const float*)d_in[0];
    const float* decoded  = (const float*)d_in[1];
    const float* w_enc    = (const float*)d_in[2];
    const float* b_enc    = (const float*)d_in[3];
    const float* w_dec    = (const float*)d_in[4];
    const float* b_dec    = (const float*)d_in[5];
    const float* w_agg    = (const float*)d_in[6];
    const float* b_agg    = (const float*)d_in[7];
    const float* w_val    = (const float*)d_in[8];
    const float* b_val    = (const float*)d_in[9];
    const float* w_attn   = (const float*)d_in[10];
    const float* b_attn   = (const float*)d_in[11];
    float* out = (float*)d_out;

    repack_kernel<<<416, 256>>>(w_val, w_dec, w_enc, w_attn);

    const int SMEM_MEGA = (100 * 68 + 100 * 68 + 64 * 68 + 32 * 66 * 2) * 4;
    cudaFuncSetAttribute(mega_kernel,
                         cudaFuncAttributeMaxDynamicSharedMemorySize, SMEM_MEGA);
    mega_kernel<<<NCTA, 256, SMEM_MEGA>>>(
        decoded, b_val, b_dec, contexts, b_enc,
        w_agg, b_agg, b_attn, out);
}

// round 8
// speedup vs baseline: 1.2114x; 1.0581x over previous
#include <cuda_runtime.h>

#define HH 96
#define WW 96
#define HW 9216
#define NE 64
#define ND 128
#define NK 4
#define NB 2
#define NCTA 296
#define N_CONV 288
#define N_KEYS 576
#define N_POOL (N_CONV + N_KEYS)

typedef unsigned long long ull;

// scratch — pixel-major [img][pix][e] layouts
__device__ float g_queries[NB * HW * NE];
__device__ float g_keys[NK * NB * HW * NE];
__device__ float g_values[NB * HW * NE];
__device__ float g_ctxT[NK * NB * HW * NE];
__device__ float g_wpack[ND * 9 * NE];        // [ci][tap][o]
__device__ float g_wdecT[ND * NE];            // [ci][o]
__device__ float g_wencT[NE * NE];            // [ci][o]
__device__ float g_wattnT2[5 * 32 * NE * 2];  // [phase][ipair][o][2]
__device__ unsigned g_bar;
__device__ unsigned g_work;

__device__ __forceinline__ ull fma2(ull a, ull b, ull c) {
    ull d;
    asm("fma.rn.f32x2 %0, %1, %2, %3;" : "=l"(d) : "l"(a), "l"(b), "l"(c));
    return d;
}
__device__ __forceinline__ ull pack2(float x, float y) {
    ull r; asm("mov.b64 %0, {%1, %2};" : "=l"(r) : "f"(x), "f"(y)); return r;
}
__device__ __forceinline__ float2 unpack2(ull v) {
    float lo, hi; asm("mov.b64 {%0, %1}, %2;" : "=f"(lo), "=f"(hi) : "l"(v));
    return make_float2(lo, hi);
}
__device__ __forceinline__ float tanh_fast(float x) {
    float y; asm("tanh.approx.f32 %0, %1;" : "=f"(y) : "f"(x)); return y;
}

// ============================================================
// repack: weight layouts + counters reset (runs before mega).
// ============================================================
__global__ void __launch_bounds__(256) repack_kernel(
    const float* __restrict__ wv, const float* __restrict__ wd,
    const float* __restrict__ we, const float* __restrict__ wa)
{
    int i = blockIdx.x * 256 + threadIdx.x;
    if (i == 0) { g_bar = 0u; g_work = 0u; }
    if (i < 73728) {
        int o = i & 63; int t = i >> 6; int tap = t % 9; int ci = t / 9;
        g_wpack[i] = wv[(size_t)o * (ND * 9) + ci * 9 + tap];
    } else if (i < 81920) {
        int r = i - 73728; int o = r & 63; int ci = r >> 6;
        g_wdecT[r] = wd[o * ND + ci];
    } else if (i < 86016) {
        int r = i - 81920; int o = r & 63; int ci = r >> 6;
        g_wencT[r] = we[o * NE + ci];
    } else if (i < 106496) {
        int r = i - 86016;
        int half = r & 1; int r2 = r >> 1;
        int o = r2 & 63; int t = r2 >> 6; int ip = t & 31; int k = t >> 5;
        g_wattnT2[r] = wa[o * 320 + k * 64 + 2 * ip + half];
    }
}

// ============================================================
// phase-A tile workers (called from mega work loop)
// ============================================================
__device__ void conv_tile(
    float* sm, int tile,
    const float* __restrict__ decoded,
    const float* __restrict__ bias_v, const float* __restrict__ bias_q)
{
    float* xs = sm;             // [16][112]
    float* ws = sm + 1792;      // [16*9][64]
    float* wq = sm + 11008;     // [16][64]
    int tid = threadIdx.x, lane = tid & 31, cg = tid >> 5;
    int b = tile / 144; int t = tile % 144;
    int yo = (t / 12) * 8, xo = (t % 12) * 8;
    int prow = lane >> 2, pcol0 = (lane & 3) * 2;
    const float* xb = decoded + (size_t)b * ND * HW;

    ull accv[4][2], accq[4][2];
#pragma unroll
    for (int ep = 0; ep < 4; ep++) {
        accv[ep][0] = accv[ep][1] = 0ull;
        accq[ep][0] = accq[ep][1] = 0ull;
    }
    for (int c0 = 0; c0 < ND; c0 += 16) {
        for (int lin = tid; lin < 1600; lin += 256) {
            int hc = lin % 10; int tt = lin / 10; int hr = tt % 10; int ci = tt / 10;
            int gy = yo - 1 + hr, gx = xo - 1 + hc;
            float v = 0.f;
            if ((unsigned)gy < HH && (unsigned)gx < WW)
                v = xb[(size_t)(c0 + ci) * HW + gy * WW + gx];
            xs[ci * 112 + hr * 11 + hc] = v;
        }
#pragma unroll
        for (int r = 0; r < 9; r++)
            ((float4*)ws)[tid + r * 256] =
                ((const float4*)(g_wpack + c0 * 576))[tid + r * 256];
        ((float4*)wq)[tid] = ((const float4*)(g_wdecT + c0 * 64))[tid];
        __syncthreads();
#pragma unroll
        for (int ci = 0; ci < 16; ci++) {
#pragma unroll
            for (int dr = 0; dr < 3; dr++) {
                int rb = ci * 112 + (prow + dr) * 11 + pcol0;
                float x0 = xs[rb], x1 = xs[rb + 1];
                float x2 = xs[rb + 2], x3 = xs[rb + 3];
                ull sx[4] = {pack2(x0, x0), pack2(x1, x1),
                             pack2(x2, x2), pack2(x3, x3)};
#pragma unroll
                for (int dc = 0; dc < 3; dc++) {
                    const float* wp = ws + (ci * 9 + dr * 3 + dc) * 64 + cg * 8;
                    ulonglong2 wA = *(const ulonglong2*)wp;
                    ulonglong2 wB = *(const ulonglong2*)(wp + 4);
                    accv[0][0] = fma2(wA.x, sx[dc], accv[0][0]);
                    accv[0][1] = fma2(wA.x, sx[dc + 1], accv[0][1]);
                    accv[1][0] = fma2(wA.y, sx[dc], accv[1][0]);
                    accv[1][1] = fma2(wA.y, sx[dc + 1], accv[1][1]);
                    accv[2][0] = fma2(wB.x, sx[dc], accv[2][0]);
                    accv[2][1] = fma2(wB.x, sx[dc + 1], accv[2][1]);
                    accv[3][0] = fma2(wB.y, sx[dc], accv[3][0]);
                    accv[3][1] = fma2(wB.y, sx[dc + 1], accv[3][1]);
                }
                if (dr == 1) {
                    const float* qp = wq + ci * 64 + cg * 8;
                    ulonglong2 qa = *(const ulonglong2*)qp;
                    ulonglong2 qb = *(const ulonglong2*)(qp + 4);
                    accq[0][0] = fma2(qa.x, sx[1], accq[0][0]);
                    accq[0][1] = fma2(qa.x, sx[2], accq[0][1]);
                    accq[1][0] = fma2(qa.y, sx[1], accq[1][0]);
                    accq[1][1] = fma2(qa.y, sx[2], accq[1][1]);
                    accq[2][0] = fma2(qb.x, sx[1], accq[2][0]);
                    accq[2][1] = fma2(qb.x, sx[2], accq[2][1]);
                    accq[3][0] = fma2(qb.y, sx[1], accq[3][0]);
                    accq[3][1] = fma2(qb.y, sx[2], accq[3][1]);
                }
            }
        }
        __syncthreads();
    }
    float4 bva = *(const float4*)&bias_v[cg * 8];
    float4 bvb = *(const float4*)&bias_v[cg * 8 + 4];
    float4 bqa = *(const float4*)&bias_q[cg * 8];
    float4 bqb = *(const float4*)&bias_q[cg * 8 + 4];
    int gp0 = (yo + prow) * WW + xo + pcol0;
#pragma unroll
    for (int pxi = 0; pxi < 2; pxi++) {
        float2 u0 = unpack2(accv[0][pxi]), u1 = unpack2(accv[1][pxi]);
        float2 u2 = unpack2(accv[2][pxi]), u3 = unpack2(accv[3][pxi]);
        float* dv = &g_values[((size_t)b * HW + gp0 + pxi) * NE + cg * 8];
        *(float4*)dv = make_float4(u0.x + bva.x, u0.y + bva.y, u1.x + bva.z, u1.y + bva.w);
        *(float4*)(dv + 4) = make_float4(u2.x + bvb.x, u2.y + bvb.y, u3.x + bvb.z, u3.y + bvb.w);
        float2 q0 = unpack2(accq[0][pxi]), q1 = unpack2(accq[1][pxi]);
        float2 q2 = unpack2(accq[2][pxi]), q3 = unpack2(accq[3][pxi]);
        float* dq = &g_queries[((size_t)b * HW + gp0 + pxi) * NE + cg * 8];
        *(float4*)dq = make_float4(q0.x + bqa.x, q0.y + bqa.y, q1.x + bqa.z, q1.y + bqa.w);
        *(float4*)(dq + 4) = make_float4(q2.x + bqb.x, q2.y + bqb.y, q3.x + bqb.z, q3.y + bqb.w);
    }
}

__device__ void keys_tile(
    float* sm, int kt,
    const float* __restrict__ contexts, const float* __restrict__ bias_k)
{
    float* xs = sm;           // [16][128]
    float* ws = sm + 2048;    // [16][64]
    int tid = threadIdx.x, lane = tid & 31, cg = tid >> 5;
    int img = kt / 72;
    int p0 = (kt % 72) * 128;
    const float* xb = contexts + (size_t)img * NE * HW + p0;
    int tpx = tid >> 1, thalf = tid & 1;

    ull acc2[4][4];
#pragma unroll
    for (int ep = 0; ep < 4; ep++)
#pragma unroll
        for (int px = 0; px < 4; px++) acc2[ep][px] = 0ull;

    for (int c0 = 0; c0 < NE; c0 += 16) {
#pragma unroll
        for (int rr = 0; rr < 2; rr++) {
            int lin = tid + rr * 256;
            int ci = lin >> 5, px4 = (lin & 31) * 4;
            *(float4*)&xs[ci * 128 + px4] =
                *(const float4*)&xb[(size_t)(c0 + ci) * HW + px4];
        }
        ((float4*)ws)[tid] = ((const float4*)(g_wencT + c0 * 64))[tid];
        __syncthreads();
        {
            float v[8];
#pragma unroll
            for (int t = 0; t < 8; t++) v[t] = xs[(thalf * 8 + t) * 128 + tpx];
            float* cd = &g_ctxT[((size_t)img * HW + p0 + tpx) * NE + c0 + thalf * 8];
            *(float4*)cd = make_float4(v[0], v[1], v[2], v[3]);
            *(float4*)(cd + 4) = make_float4(v[4], v[5], v[6], v[7]);
        }
#pragma unroll
        for (int ci = 0; ci < 16; ci++) {
            float4 xv = *(float4*)&xs[ci * 128 + lane * 4];
            ull sx[4] = {pack2(xv.x, xv.x), pack2(xv.y, xv.y),
                         pack2(xv.z, xv.z), pack2(xv.w, xv.w)};
            ulonglong2 wA = *(const ulonglong2*)&ws[ci * 64 + cg * 8];
            ulonglong2 wB = *(const ulonglong2*)&ws[ci * 64 + cg * 8 + 4];
#pragma unroll
            for (int px = 0; px < 4; px++) {
                acc2[0][px] = fma2(wA.x, sx[px], acc2[0][px]);
                acc2[1][px] = fma2(wA.y, sx[px], acc2[1][px]);
                acc2[2][px] = fma2(wB.x, sx[px], acc2[2][px]);
                acc2[3][px] = fma2(wB.y, sx[px], acc2[3][px]);
            }
        }
        __syncthreads();
    }
    float4 ba = *(const float4*)&bias_k[cg * 8];
    float4 bb = *(const float4*)&bias_k[cg * 8 + 4];
#pragma unroll
    for (int px = 0; px < 4; px++) {
        float2 u0 = unpack2(acc2[0][px]), u1 = unpack2(acc2[1][px]);
        float2 u2 = unpack2(acc2[2][px]), u3 = unpack2(acc2[3][px]);
        float* dst = &g_keys[((size_t)img * HW + p0 + lane * 4 + px) * NE + cg * 8];
        *(float4*)dst = make_float4(u0.x + ba.x, u0.y + ba.y, u1.x + ba.z, u1.y + ba.w);
        *(float4*)(dst + 4) = make_float4(u2.x + bb.x, u2.y + bb.y, u3.x + bb.z, u3.y + bb.w);
    }
}

// ============================================================
__device__ __forceinline__ void final_accum(
    const float* __restrict__ cat, const ull* __restrict__ wsl2,
    int lane, int wr, ull acc0[8], ull acc1[8])
{
#pragma unroll
    for (int it = 0; it < 8; it++) {
        ull w0[4], w1[4];
#pragma unroll
        for (int t = 0; t < 4; t++) {
            int ip = it * 4 + t;
            w0[t] = wsl2[ip * 66 + lane];
            w1[t] = wsl2[ip * 66 + 32 + lane];
        }
#pragma unroll
        for (int j = 0; j < 8; j++) {
            const ull* cp = (const ull*)&cat[(wr * 8 + j) * 68 + it * 8];
            ulonglong2 cA = *(const ulonglong2*)cp;
            ulonglong2 cB = *(const ulonglong2*)(cp + 2);
            ull a0 = acc0[j];
            a0 = fma2(w0[0], cA.x, a0); a0 = fma2(w0[1], cA.y, a0);
            a0 = fma2(w0[2], cB.x, a0); a0 = fma2(w0[3], cB.y, a0);
            acc0[j] = a0;
            ull a1 = acc1[j];
            a1 = fma2(w1[0], cA.x, a1); a1 = fma2(w1[1], cA.y, a1);
            a1 = fma2(w1[2], cB.x, a1); a1 = fma2(w1[3], cB.y, a1);
            acc1[j] = a1;
        }
    }
}

// ============================================================
// MEGA kernel: dynamic phase-A pool, barrier, static attn.
// grid = 296 = 2 CTAs x 148 SMs (all resident; spin-safe).
// ============================================================
__global__ void __launch_bounds__(256, 2) mega_kernel(
    const float* __restrict__ decoded,
    const float* __restrict__ bias_v,
    const float* __restrict__ bias_q,
    const float* __restrict__ contexts,
    const float* __restrict__ bias_k,
    const float* __restrict__ w_agg,
    const float* __restrict__ b_agg_p,
    const float* __restrict__ b_attn,
    float* __restrict__ out)
{
    extern __shared__ __align__(16) float sm[];
    __shared__ int s_idx;
    int c = blockIdx.x;
    int tid = threadIdx.x, lane = tid & 31, cg = tid >> 5;

    // ================= phase A: dynamic work pool =================
    for (;;) {
        __syncthreads();
        if (tid == 0) s_idx = (int)atomicAdd(&g_work, 1u);
        __syncthreads();
        int idx = s_idx;
        if (idx >= N_POOL) break;
        if (idx < N_CONV)
            conv_tile(sm, idx, decoded, bias_v, bias_q);
        else
            keys_tile(sm, idx - N_CONV, contexts, bias_k);
    }

    // ================= device-wide barrier =================
    if (tid == 0) {
        __threadfence();
        atomicAdd(&g_bar, 1u);
        unsigned v;
        do {
            asm volatile("ld.acquire.gpu.global.u32 %0, [%1];"
                         : "=r"(v) : "l"(&g_bar));
        } while (v < NCTA);
    }
    __syncthreads();

    // ================= phase B: attention + projection =================
    if (c >= N_CONV) return;
    {
        float* ks  = sm;                    // [100][68]
        float* cs  = ks + 100 * 68;         // [100][68]
        float* cat = cs + 100 * 68;         // [64][68]
        ull* wsl2  = (ull*)(cat + 64 * 68); // [32][66]

        int b = c / 144; int t = c % 144;
        int yo = (t / 12) * 8, xo = (t % 12) * 8;
        int wr = cg;
        int j = lane >> 2, eq = lane & 3;
        int pix = wr * 8 + j;
        float bagg = b_agg_p[0];

        {
            const float* vb = g_values + (size_t)b * HW * NE;
            for (int lin = tid; lin < 1024; lin += 256) {
                int p = lin >> 4, e4 = (lin & 15) * 4;
                int gp = (yo + (p >> 3)) * WW + xo + (p & 7);
                *(float4*)&cat[p * 68 + e4] = *(const float4*)&vb[(size_t)gp * NE + e4];
            }
            const ulonglong2* wsrc = (const ulonglong2*)g_wattnT2;
            for (int lin = tid; lin < 1024; lin += 256) {
                ulonglong2 u = wsrc[lin];
                int o2 = (lin & 31) * 2, ip = lin >> 5;
                *(ulonglong2*)&wsl2[ip * 66 + o2] = u;
            }
        }
        float qreg[16], waggr[16];
        {
            const float* qb = g_queries +
                ((size_t)b * HW + (yo + wr) * WW + xo + j) * NE + eq * 16;
#pragma unroll
            for (int u = 0; u < 4; u++) {
                float4 qv = *(const float4*)(qb + u * 4);
                qreg[u*4] = qv.x; qreg[u*4+1] = qv.y; qreg[u*4+2] = qv.z; qreg[u*4+3] = qv.w;
                float4 wv2 = *(const float4*)&w_agg[eq * 16 + u * 4];
                waggr[u*4] = wv2.x; waggr[u*4+1] = wv2.y; waggr[u*4+2] = wv2.z; waggr[u*4+3] = wv2.w;
            }
        }
        __syncthreads();

        ull acc0[8], acc1[8];
#pragma unroll
        for (int t2 = 0; t2 < 8; t2++) { acc0[t2] = 0ull; acc1[t2] = 0ull; }
        final_accum(cat, wsl2, lane, wr, acc0, acc1);

        for (int k = 0; k < NK; k++) {
            __syncthreads();
            const float* kb = g_keys + (size_t)(k * NB + b) * HW * NE;
            const float* cb = g_ctxT + (size_t)(k * NB + b) * HW * NE;
            for (int lin = tid; lin < 1600; lin += 256) {
                int hp = lin >> 4, e4 = (lin & 15) * 4;
                int hr = hp / 10, hc = hp % 10;
                int gy = yo - 1 + hr, gx = xo - 1 + hc;
                float4 kv = make_float4(0.f, 0.f, 0.f, 0.f), cv = kv;
                if ((unsigned)gy < HH && (unsigned)gx < WW) {
                    size_t off = ((size_t)gy * WW + gx) * NE + e4;
                    kv = *(const float4*)&kb[off];
                    cv = *(const float4*)&cb[off];
                }
                *(float4*)&ks[hp * 68 + e4] = kv;
                *(float4*)&cs[hp * 68 + e4] = cv;
            }
            const ulonglong2* wsrc = (const ulonglong2*)g_wattnT2 + (k + 1) * 1024;
            for (int lin = tid; lin < 1024; lin += 256) {
                ulonglong2 u = wsrc[lin];
                int o2 = (lin & 31) * 2, ip = lin >> 5;
                *(ulonglong2*)&wsl2[ip * 66 + o2] = u;
            }
            __syncthreads();

            int base_hp = wr * 10 + j;
            float s[9];
#pragma unroll
            for (int n = 0; n < 9; n++) {
                const int dr = n / 3, dc = n % 3;
                const float* kp = &ks[(base_hp + dr * 10 + dc) * 68 + eq * 16];
                float pa = 0.f, pb = 0.f;
#pragma unroll
                for (int u = 0; u < 2; u++) {
                    float4 k0 = *(const float4*)(kp + u * 8);
                    float4 k1 = *(const float4*)(kp + u * 8 + 4);
                    pa = fmaf(waggr[u*8+0], tanh_fast(qreg[u*8+0] + k0.x), pa);
                    pb = fmaf(waggr[u*8+1], tanh_fast(qreg[u*8+1] + k0.y), pb);
                    pa = fmaf(waggr[u*8+2], tanh_fast(qreg[u*8+2] + k0.z), pa);
                    pb = fmaf(waggr[u*8+3], tanh_fast(qreg[u*8+3] + k0.w), pb);
                    pa = fmaf(waggr[u*8+4], tanh_fast(qreg[u*8+4] + k1.x), pa);
                    pb = fmaf(waggr[u*8+5], tanh_fast(qreg[u*8+5] + k1.y), pb);
                    pa = fmaf(waggr[u*8+6], tanh_fast(qreg[u*8+6] + k1.z), pa);
                    pb = fmaf(waggr[u*8+7], tanh_fast(qreg[u*8+7] + k1.w), pb);
                }
                float part = pa + pb;
                part += __shfl_xor_sync(0xffffffffu, part, 1);
                part += __shfl_xor_sync(0xffffffffu, part, 2);
                bool valid = ((unsigned)(yo + wr + dr - 1) < HH) &&
                             ((unsigned)(xo + j + dc - 1) < WW);
                s[n] = valid ? part + bagg : -1e30f;
            }
            float m = s[0];
#pragma unroll
            for (int n = 1; n < 9; n++) m = fmaxf(m, s[n]);
            float p[9], ps = 0.f;
#pragma unroll
            for (int n = 0; n < 9; n++) { p[n] = __expf(s[n] - m); ps += p[n]; }
            float rinv = __fdividef(1.f, ps);

            ull a2[8];
#pragma unroll
            for (int t2 = 0; t2 < 8; t2++) a2[t2] = 0ull;
#pragma unroll
            for (int n = 0; n < 9; n++) {
                const int dr = n / 3, dc = n % 3;
                float pn = p[n] * rinv;
                ull pr = pack2(pn, pn);
                const float* cp = &cs[(base_hp + dr * 10 + dc) * 68 + eq * 16];
                ulonglong2 cA = *(const ulonglong2*)cp;
                ulonglong2 cB = *(const ulonglong2*)(cp + 4);
                ulonglong2 cC = *(const ulonglong2*)(cp + 8);
                ulonglong2 cD = *(const ulonglong2*)(cp + 12);
                a2[0] = fma2(pr, cA.x, a2[0]); a2[1] = fma2(pr, cA.y, a2[1]);
                a2[2] = fma2(pr, cB.x, a2[2]); a2[3] = fma2(pr, cB.y, a2[3]);
                a2[4] = fma2(pr, cC.x, a2[4]); a2[5] = fma2(pr, cC.y, a2[5]);
                a2[6] = fma2(pr, cD.x, a2[6]); a2[7] = fma2(pr, cD.y, a2[7]);
            }
            {
                float* dp = &cat[pix * 68 + eq * 16];
                ulonglong2 t0; t0.x = a2[0]; t0.y = a2[1]; *(ulonglong2*)dp = t0;
                ulonglong2 t1; t1.x = a2[2]; t1.y = a2[3]; *(ulonglong2*)(dp + 4) = t1;
                ulonglong2 t2; t2.x = a2[4]; t2.y = a2[5]; *(ulonglong2*)(dp + 8) = t2;
                ulonglong2 t3; t3.x = a2[6]; t3.y = a2[7]; *(ulonglong2*)(dp + 12) = t3;
            }
            __syncwarp();
            final_accum(cat, wsl2, lane, wr, acc0, acc1);
        }

        float ba0 = b_attn[lane], ba1 = b_attn[lane + 32];
        __syncthreads();
#pragma unroll
        for (int t2 = 0; t2 < 8; t2++) {
            int px = wr * 8 + t2;
            float2 z0 = unpack2(acc0[t2]);
            float2 z1 = unpack2(acc1[t2]);
            float r0 = z0.x + z0.y + ba0; r0 = (r0 >= 0.f) ? r0 : 0.2f * r0;
            float r1 = z1.x + z1.y + ba1; r1 = (r1 >= 0.f) ? r1 : 0.2f * r1;
            cat[px * 68 + lane] = r0;
            cat[px * 68 + 32 + lane] = r1;
        }
        __syncthreads();
        for (int lin = tid; lin < 4096; lin += 256) {
            int col = lin & 7, row = (lin >> 3) & 7, e = lin >> 6;
            out[(b * NE + e) * HW + (yo + row) * WW + xo + col] =
                cat[(row * 8 + col) * 68 + e];
        }
    }
}

// ============================================================
extern "C" void kernel_launch(void* const* d_in, const int* in_sizes, int n_in,
                              void* d_out, int out_size)
{
    (void)in_sizes; (void)n_in; (void)out_size;
    const float* contexts = (const float*)d_in[0];
    const float* decoded  = (const float*)d_in[1];
    const float* w_enc    = (const float*)d_in[2];
    const float* b_enc    = (const float*)d_in[3];
    const float* w_dec    = (const float*)d_in[4];
    const float* b_dec    = (const float*)d_in[5];
    const float* w_agg    = (const float*)d_in[6];
    const float* b_agg    = (const float*)d_in[7];
    const float* w_val    = (const float*)d_in[8];
    const float* b_val    = (const float*)d_in[9];
    const float* w_attn   = (const float*)d_in[10];
    const float* b_attn   = (const float*)d_in[11];
    float* out = (float*)d_out;

    repack_kernel<<<416, 256>>>(w_val, w_dec, w_enc, w_attn);

    const int SMEM_MEGA = (100 * 68 + 100 * 68 + 64 * 68 + 32 * 66 * 2) * 4;
    cudaFuncSetAttribute(mega_kernel,
                         cudaFuncAttributeMaxDynamicSharedMemorySize, SMEM_MEGA);
    mega_kernel<<<NCTA, 256, SMEM_MEGA>>>(
        decoded, b_val, b_dec, contexts, b_enc,
        w_agg, b_agg, b_attn, out);
}

// round 9
// speedup vs baseline: 1.2169x; 1.0045x over previous
#include <cuda_runtime.h>

#define HH 96
#define WW 96
#define HW 9216
#define NE 64
#define ND 128
#define NK 4
#define NB 2
#define NCTA 296
#define N_CONV 144
#define N_Q 144
#define N_KEYS 576
#define N_POOL (N_CONV + N_Q + N_KEYS)

typedef unsigned long long ull;

// scratch — pixel-major [img][pix][e] layouts
__device__ float g_queries[NB * HW * NE];
__device__ float g_keys[NK * NB * HW * NE];
__device__ float g_values[NB * HW * NE];
__device__ float g_ctxT[NK * NB * HW * NE];
__device__ float g_wpack[ND * 9 * NE];        // [ci][tap][o]
__device__ float g_wdecT[ND * NE];            // [ci][o]
__device__ float g_wencT[NE * NE];            // [ci][o]
__device__ float g_wattnT2[5 * 32 * NE * 2];  // [phase][ipair][o][2]
__device__ unsigned g_bar;
__device__ unsigned g_work;

__device__ __forceinline__ ull fma2(ull a, ull b, ull c) {
    ull d;
    asm("fma.rn.f32x2 %0, %1, %2, %3;" : "=l"(d) : "l"(a), "l"(b), "l"(c));
    return d;
}
__device__ __forceinline__ ull pack2(float x, float y) {
    ull r; asm("mov.b64 %0, {%1, %2};" : "=l"(r) : "f"(x), "f"(y)); return r;
}
__device__ __forceinline__ float2 unpack2(ull v) {
    float lo, hi; asm("mov.b64 {%0, %1}, %2;" : "=f"(lo), "=f"(hi) : "l"(v));
    return make_float2(lo, hi);
}
__device__ __forceinline__ float tanh_fast(float x) {
    float y; asm("tanh.approx.f32 %0, %1;" : "=f"(y) : "f"(x)); return y;
}

// ============================================================
__global__ void __launch_bounds__(256) repack_kernel(
    const float* __restrict__ wv, const float* __restrict__ wd,
    const float* __restrict__ we, const float* __restrict__ wa)
{
    int i = blockIdx.x * 256 + threadIdx.x;
    if (i == 0) { g_bar = 0u; g_work = 0u; }
    if (i < 73728) {
        int o = i & 63; int t = i >> 6; int tap = t % 9; int ci = t / 9;
        g_wpack[i] = wv[(size_t)o * (ND * 9) + ci * 9 + tap];
    } else if (i < 81920) {
        int r = i - 73728; int o = r & 63; int ci = r >> 6;
        g_wdecT[r] = wd[o * ND + ci];
    } else if (i < 86016) {
        int r = i - 81920; int o = r & 63; int ci = r >> 6;
        g_wencT[r] = we[o * NE + ci];
    } else if (i < 106496) {
        int r = i - 86016;
        int half = r & 1; int r2 = r >> 1;
        int o = r2 & 63; int t = r2 >> 6; int ip = t & 31; int k = t >> 5;
        g_wattnT2[r] = wa[o * 320 + k * 64 + 2 * ip + half];
    }
}

// ============================================================
// conv3x3 tile: 16 wide x 8 tall, 4 px per thread, 4 e-pairs.
// ============================================================
__device__ void conv_tile(
    float* sm, int tile,
    const float* __restrict__ decoded,
    const float* __restrict__ bias_v)
{
    float* xs = sm;             // [16 ci][10 r][20 (18 used)]
    float* ws = sm + 3200;      // [16*9][64]
    int tid = threadIdx.x, lane = tid & 31, cg = tid >> 5;
    int b = tile / 72; int t = tile % 72;
    int yo = (t / 6) * 8, xo = (t % 6) * 16;
    int prow = lane >> 2, pcol0 = (lane & 3) * 4;
    const float* xb = decoded + (size_t)b * ND * HW;

    ull accv[4][4];
#pragma unroll
    for (int ep = 0; ep < 4; ep++)
#pragma unroll
        for (int px = 0; px < 4; px++) accv[ep][px] = 0ull;

    for (int c0 = 0; c0 < ND; c0 += 16) {
        for (int lin = tid; lin < 2880; lin += 256) {
            int hc = lin % 18; int tt = lin / 18; int hr = tt % 10; int ci = tt / 10;
            int gy = yo - 1 + hr, gx = xo - 1 + hc;
            float v = 0.f;
            if ((unsigned)gy < HH && (unsigned)gx < WW)
                v = xb[(size_t)(c0 + ci) * HW + gy * WW + gx];
            xs[ci * 200 + hr * 20 + hc] = v;
        }
#pragma unroll
        for (int r = 0; r < 9; r++)
            ((float4*)ws)[tid + r * 256] =
                ((const float4*)(g_wpack + c0 * 576))[tid + r * 256];
        __syncthreads();
#pragma unroll
        for (int ci = 0; ci < 16; ci++) {
#pragma unroll
            for (int dr = 0; dr < 3; dr++) {
                int rb = ci * 200 + (prow + dr) * 20 + pcol0;
                float4 xA = *(const float4*)&xs[rb];
                float2 xB = *(const float2*)&xs[rb + 4];
                ull sx[6] = {pack2(xA.x, xA.x), pack2(xA.y, xA.y),
                             pack2(xA.z, xA.z), pack2(xA.w, xA.w),
                             pack2(xB.x, xB.x), pack2(xB.y, xB.y)};
#pragma unroll
                for (int dc = 0; dc < 3; dc++) {
                    const float* wp = ws + (ci * 9 + dr * 3 + dc) * 64 + cg * 8;
                    ulonglong2 wA = *(const ulonglong2*)wp;
                    ulonglong2 wB = *(const ulonglong2*)(wp + 4);
#pragma unroll
                    for (int px = 0; px < 4; px++) {
                        accv[0][px] = fma2(wA.x, sx[dc + px], accv[0][px]);
                        accv[1][px] = fma2(wA.y, sx[dc + px], accv[1][px]);
                        accv[2][px] = fma2(wB.x, sx[dc + px], accv[2][px]);
                        accv[3][px] = fma2(wB.y, sx[dc + px], accv[3][px]);
                    }
                }
            }
        }
        __syncthreads();
    }
    float4 bva = *(const float4*)&bias_v[cg * 8];
    float4 bvb = *(const float4*)&bias_v[cg * 8 + 4];
    int gp0 = (yo + prow) * WW + xo + pcol0;
#pragma unroll
    for (int px = 0; px < 4; px++) {
        float2 u0 = unpack2(accv[0][px]), u1 = unpack2(accv[1][px]);
        float2 u2 = unpack2(accv[2][px]), u3 = unpack2(accv[3][px]);
        float* dv = &g_values[((size_t)b * HW + gp0 + px) * NE + cg * 8];
        *(float4*)dv = make_float4(u0.x + bva.x, u0.y + bva.y, u1.x + bva.z, u1.y + bva.w);
        *(float4*)(dv + 4) = make_float4(u2.x + bvb.x, u2.y + bvb.y, u3.x + bvb.z, u3.y + bvb.w);
    }
}

// ============================================================
// 1x1 conv tile (keys: CIN=64 + ctxT transpose; queries: CIN=128).
// 128 px x 64 out per tile.
// ============================================================
template <int CIN, bool DOCTX>
__device__ void tile1x1(
    float* sm, int tile,
    const float* __restrict__ x, const float* __restrict__ wsrc,
    const float* __restrict__ bias,
    float* __restrict__ outp, float* __restrict__ outc)
{
    float* xs = sm;           // [16][128]
    float* ws = sm + 2048;    // [16][64]
    int tid = threadIdx.x, lane = tid & 31, cg = tid >> 5;
    int img = tile / 72;
    int p0 = (tile % 72) * 128;
    const float* xb = x + (size_t)img * CIN * HW + p0;
    int tpx = tid >> 1, thalf = tid & 1;

    ull acc2[4][4];
#pragma unroll
    for (int ep = 0; ep < 4; ep++)
#pragma unroll
        for (int px = 0; px < 4; px++) acc2[ep][px] = 0ull;

    for (int c0 = 0; c0 < CIN; c0 += 16) {
#pragma unroll
        for (int rr = 0; rr < 2; rr++) {
            int lin = tid + rr * 256;
            int ci = lin >> 5, px4 = (lin & 31) * 4;
            *(float4*)&xs[ci * 128 + px4] =
                *(const float4*)&xb[(size_t)(c0 + ci) * HW + px4];
        }
        ((float4*)ws)[tid] = ((const float4*)(wsrc + c0 * 64))[tid];
        __syncthreads();
        if (DOCTX) {
            float v[8];
#pragma unroll
            for (int t = 0; t < 8; t++) v[t] = xs[(thalf * 8 + t) * 128 + tpx];
            float* cd = &outc[((size_t)img * HW + p0 + tpx) * NE + c0 + thalf * 8];
            *(float4*)cd = make_float4(v[0], v[1], v[2], v[3]);
            *(float4*)(cd + 4) = make_float4(v[4], v[5], v[6], v[7]);
        }
#pragma unroll
        for (int ci = 0; ci < 16; ci++) {
            float4 xv = *(float4*)&xs[ci * 128 + lane * 4];
            ull sx[4] = {pack2(xv.x, xv.x), pack2(xv.y, xv.y),
                         pack2(xv.z, xv.z), pack2(xv.w, xv.w)};
            ulonglong2 wA = *(const ulonglong2*)&ws[ci * 64 + cg * 8];
            ulonglong2 wB = *(const ulonglong2*)&ws[ci * 64 + cg * 8 + 4];
#pragma unroll
            for (int px = 0; px < 4; px++) {
                acc2[0][px] = fma2(wA.x, sx[px], acc2[0][px]);
                acc2[1][px] = fma2(wA.y, sx[px], acc2[1][px]);
                acc2[2][px] = fma2(wB.x, sx[px], acc2[2][px]);
                acc2[3][px] = fma2(wB.y, sx[px], acc2[3][px]);
            }
        }
        __syncthreads();
    }
    float4 ba = *(const float4*)&bias[cg * 8];
    float4 bb = *(const float4*)&bias[cg * 8 + 4];
#pragma unroll
    for (int px = 0; px < 4; px++) {
        float2 u0 = unpack2(acc2[0][px]), u1 = unpack2(acc2[1][px]);
        float2 u2 = unpack2(acc2[2][px]), u3 = unpack2(acc2[3][px]);
        float* dst = &outp[((size_t)img * HW + p0 + lane * 4 + px) * NE + cg * 8];
        *(float4*)dst = make_float4(u0.x + ba.x, u0.y + ba.y, u1.x + ba.z, u1.y + ba.w);
        *(float4*)(dst + 4) = make_float4(u2.x + bb.x, u2.y + bb.y, u3.x + bb.z, u3.y + bb.w);
    }
}

// ============================================================
__device__ __forceinline__ void final_accum(
    const float* __restrict__ cat, const ull* __restrict__ wsl2,
    int lane, int wr, ull acc0[8], ull acc1[8])
{
#pragma unroll
    for (int it = 0; it < 8; it++) {
        ull w0[4], w1[4];
#pragma unroll
        for (int t = 0; t < 4; t++) {
            int ip = it * 4 + t;
            w0[t] = wsl2[ip * 66 + lane];
            w1[t] = wsl2[ip * 66 + 32 + lane];
        }
#pragma unroll
        for (int j = 0; j < 8; j++) {
            const ull* cp = (const ull*)&cat[(wr * 8 + j) * 68 + it * 8];
            ulonglong2 cA = *(const ulonglong2*)cp;
            ulonglong2 cB = *(const ulonglong2*)(cp + 2);
            ull a0 = acc0[j];
            a0 = fma2(w0[0], cA.x, a0); a0 = fma2(w0[1], cA.y, a0);
            a0 = fma2(w0[2], cB.x, a0); a0 = fma2(w0[3], cB.y, a0);
            acc0[j] = a0;
            ull a1 = acc1[j];
            a1 = fma2(w1[0], cA.x, a1); a1 = fma2(w1[1], cA.y, a1);
            a1 = fma2(w1[2], cB.x, a1); a1 = fma2(w1[3], cB.y, a1);
            acc1[j] = a1;
        }
    }
}

// ============================================================
// MEGA kernel: dynamic phase-A pool, barrier, static attn.
// ============================================================
__global__ void __launch_bounds__(256, 2) mega_kernel(
    const float* __restrict__ decoded,
    const float* __restrict__ bias_v,
    const float* __restrict__ bias_q,
    const float* __restrict__ contexts,
    const float* __restrict__ bias_k,
    const float* __restrict__ w_agg,
    const float* __restrict__ b_agg_p,
    const float* __restrict__ b_attn,
    float* __restrict__ out)
{
    extern __shared__ __align__(16) float sm[];
    __shared__ int s_idx;
    int c = blockIdx.x;
    int tid = threadIdx.x, lane = tid & 31, cg = tid >> 5;

    // ================= phase A: dynamic work pool =================
    for (;;) {
        __syncthreads();
        if (tid == 0) s_idx = (int)atomicAdd(&g_work, 1u);
        __syncthreads();
        int idx = s_idx;
        if (idx >= N_POOL) break;
        if (idx < N_CONV)
            conv_tile(sm, idx, decoded, bias_v);
        else if (idx < N_CONV + N_Q)
            tile1x1<ND, false>(sm, idx - N_CONV, decoded, g_wdecT, bias_q,
                               g_queries, (float*)0);
        else
            tile1x1<NE, true>(sm, idx - N_CONV - N_Q, contexts, g_wencT, bias_k,
                              g_keys, g_ctxT);
    }

    // ================= device-wide barrier =================
    if (tid == 0) {
        __threadfence();
        atomicAdd(&g_bar, 1u);
        unsigned v;
        do {
            asm volatile("ld.acquire.gpu.global.u32 %0, [%1];"
                         : "=r"(v) : "l"(&g_bar));
        } while (v < NCTA);
    }
    __syncthreads();

    // ================= phase B: attention + projection =================
    if (c >= 288) return;
    {
        float* ks  = sm;                    // [100][68]
        float* cs  = ks + 100 * 68;         // [100][68]
        float* cat = cs + 100 * 68;         // [64][68]
        ull* wsl2  = (ull*)(cat + 64 * 68); // [32][66]

        int b = c / 144; int t = c % 144;
        int yo = (t / 12) * 8, xo = (t % 12) * 8;
        int wr = cg;
        int j = lane >> 2, eq = lane & 3;
        int pix = wr * 8 + j;
        float bagg = b_agg_p[0];

        {
            const float* vb = g_values + (size_t)b * HW * NE;
            for (int lin = tid; lin < 1024; lin += 256) {
                int p = lin >> 4, e4 = (lin & 15) * 4;
                int gp = (yo + (p >> 3)) * WW + xo + (p & 7);
                *(float4*)&cat[p * 68 + e4] = *(const float4*)&vb[(size_t)gp * NE + e4];
            }
            const ulonglong2* wsrc = (const ulonglong2*)g_wattnT2;
            for (int lin = tid; lin < 1024; lin += 256) {
                ulonglong2 u = wsrc[lin];
                int o2 = (lin & 31) * 2, ip = lin >> 5;
                *(ulonglong2*)&wsl2[ip * 66 + o2] = u;
            }
        }
        float qreg[16], waggr[16];
        {
            const float* qb = g_queries +
                ((size_t)b * HW + (yo + wr) * WW + xo + j) * NE + eq * 16;
#pragma unroll
            for (int u = 0; u < 4; u++) {
                float4 qv = *(const float4*)(qb + u * 4);
                qreg[u*4] = qv.x; qreg[u*4+1] = qv.y; qreg[u*4+2] = qv.z; qreg[u*4+3] = qv.w;
                float4 wv2 = *(const float4*)&w_agg[eq * 16 + u * 4];
                waggr[u*4] = wv2.x; waggr[u*4+1] = wv2.y; waggr[u*4+2] = wv2.z; waggr[u*4+3] = wv2.w;
            }
        }
        __syncthreads();

        ull acc0[8], acc1[8];
#pragma unroll
        for (int t2 = 0; t2 < 8; t2++) { acc0[t2] = 0ull; acc1[t2] = 0ull; }
        final_accum(cat, wsl2, lane, wr, acc0, acc1);

        for (int k = 0; k < NK; k++) {
            __syncthreads();
            const float* kb = g_keys + (size_t)(k * NB + b) * HW * NE;
            const float* cb = g_ctxT + (size_t)(k * NB + b) * HW * NE;
            for (int lin = tid; lin < 1600; lin += 256) {
                int hp = lin >> 4, e4 = (lin & 15) * 4;
                int hr = hp / 10, hc = hp % 10;
                int gy = yo - 1 + hr, gx = xo - 1 + hc;
                float4 kv = make_float4(0.f, 0.f, 0.f, 0.f), cv = kv;
                if ((unsigned)gy < HH && (unsigned)gx < WW) {
                    size_t off = ((size_t)gy * WW + gx) * NE + e4;
                    kv = *(const float4*)&kb[off];
                    cv = *(const float4*)&cb[off];
                }
                *(float4*)&ks[hp * 68 + e4] = kv;
                *(float4*)&cs[hp * 68 + e4] = cv;
            }
            const ulonglong2* wsrc = (const ulonglong2*)g_wattnT2 + (k + 1) * 1024;
            for (int lin = tid; lin < 1024; lin += 256) {
                ulonglong2 u = wsrc[lin];
                int o2 = (lin & 31) * 2, ip = lin >> 5;
                *(ulonglong2*)&wsl2[ip * 66 + o2] = u;
            }
            __syncthreads();

            int base_hp = wr * 10 + j;
            float s[9];
#pragma unroll
            for (int n = 0; n < 9; n++) {
                const int dr = n / 3, dc = n % 3;
                const float* kp = &ks[(base_hp + dr * 10 + dc) * 68 + eq * 16];
                float pa = 0.f, pb = 0.f;
#pragma unroll
                for (int u = 0; u < 2; u++) {
                    float4 k0 = *(const float4*)(kp + u * 8);
                    float4 k1 = *(const float4*)(kp + u * 8 + 4);
                    pa = fmaf(waggr[u*8+0], tanh_fast(qreg[u*8+0] + k0.x), pa);
                    pb = fmaf(waggr[u*8+1], tanh_fast(qreg[u*8+1] + k0.y), pb);
                    pa = fmaf(waggr[u*8+2], tanh_fast(qreg[u*8+2] + k0.z), pa);
                    pb = fmaf(waggr[u*8+3], tanh_fast(qreg[u*8+3] + k0.w), pb);
                    pa = fmaf(waggr[u*8+4], tanh_fast(qreg[u*8+4] + k1.x), pa);
                    pb = fmaf(waggr[u*8+5], tanh_fast(qreg[u*8+5] + k1.y), pb);
                    pa = fmaf(waggr[u*8+6], tanh_fast(qreg[u*8+6] + k1.z), pa);
                    pb = fmaf(waggr[u*8+7], tanh_fast(qreg[u*8+7] + k1.w), pb);
                }
                float part = pa + pb;
                part += __shfl_xor_sync(0xffffffffu, part, 1);
                part += __shfl_xor_sync(0xffffffffu, part, 2);
                bool valid = ((unsigned)(yo + wr + dr - 1) < HH) &&
                             ((unsigned)(xo + j + dc - 1) < WW);
                s[n] = valid ? part + bagg : -1e30f;
            }
            float m = s[0];
#pragma unroll
            for (int n = 1; n < 9; n++) m = fmaxf(m, s[n]);
            float p[9], ps = 0.f;
#pragma unroll
            for (int n = 0; n < 9; n++) { p[n] = __expf(s[n] - m); ps += p[n]; }
            float rinv = __fdividef(1.f, ps);

            ull a2[8];
#pragma unroll
            for (int t2 = 0; t2 < 8; t2++) a2[t2] = 0ull;
#pragma unroll
            for (int n = 0; n < 9; n++) {
                const int dr = n / 3, dc = n % 3;
                float pn = p[n] * rinv;
                ull pr = pack2(pn, pn);
                const float* cp = &cs[(base_hp + dr * 10 + dc) * 68 + eq * 16];
                ulonglong2 cA = *(const ulonglong2*)cp;
                ulonglong2 cB = *(const ulonglong2*)(cp + 4);
                ulonglong2 cC = *(const ulonglong2*)(cp + 8);
                ulonglong2 cD = *(const ulonglong2*)(cp + 12);
                a2[0] = fma2(pr, cA.x, a2[0]); a2[1] = fma2(pr, cA.y, a2[1]);
                a2[2] = fma2(pr, cB.x, a2[2]); a2[3] = fma2(pr, cB.y, a2[3]);
                a2[4] = fma2(pr, cC.x, a2[4]); a2[5] = fma2(pr, cC.y, a2[5]);
                a2[6] = fma2(pr, cD.x, a2[6]); a2[7] = fma2(pr, cD.y, a2[7]);
            }
            {
                float* dp = &cat[pix * 68 + eq * 16];
                ulonglong2 t0; t0.x = a2[0]; t0.y = a2[1]; *(ulonglong2*)dp = t0;
                ulonglong2 t1; t1.x = a2[2]; t1.y = a2[3]; *(ulonglong2*)(dp + 4) = t1;
                ulonglong2 t2; t2.x = a2[4]; t2.y = a2[5]; *(ulonglong2*)(dp + 8) = t2;
                ulonglong2 t3; t3.x = a2[6]; t3.y = a2[7]; *(ulonglong2*)(dp + 12) = t3;
            }
            __syncwarp();
            final_accum(cat, wsl2, lane, wr, acc0, acc1);
        }

        float ba0 = b_attn[lane], ba1 = b_attn[lane + 32];
        __syncthreads();
#pragma unroll
        for (int t2 = 0; t2 < 8; t2++) {
            int px = wr * 8 + t2;
            float2 z0 = unpack2(acc0[t2]);
            float2 z1 = unpack2(acc1[t2]);
            float r0 = z0.x + z0.y + ba0; r0 = (r0 >= 0.f) ? r0 : 0.2f * r0;
            float r1 = z1.x + z1.y + ba1; r1 = (r1 >= 0.f) ? r1 : 0.2f * r1;
            cat[px * 68 + lane] = r0;
            cat[px * 68 + 32 + lane] = r1;
        }
        __syncthreads();
        for (int lin = tid; lin < 4096; lin += 256) {
            int col = lin & 7, row = (lin >> 3) & 7, e = lin >> 6;
            out[(b * NE + e) * HW + (yo + row) * WW + xo + col] =
                cat[(row * 8 + col) * 68 + e];
        }
    }
}

// ============================================================
extern "C" void kernel_launch(void* const* d_in, const int* in_sizes, int n_in,
                              void* d_out, int out_size)
{
    (void)in_sizes; (void)n_in; (void)out_size;
    const float* contexts = (const float*)d_in[0];
    const float* decoded  = (const float*)d_in[1];
    const float* w_enc    = (const float*)d_in[2];
    const float* b_enc    = (const float*)d_in[3];
    const float* w_dec    = (const float*)d_in[4];
    const float* b_dec    = (const float*)d_in[5];
    const float* w_agg    = (const float*)d_in[6];
    const float* b_agg    = (const float*)d_in[7];
    const float* w_val    = (const float*)d_in[8];
    const float* b_val    = (const float*)d_in[9];
    const float* w_attn   = (const float*)d_in[10];
    const float* b_attn   = (const float*)d_in[11];
    float* out = (float*)d_out;

    repack_kernel<<<416, 256>>>(w_val, w_dec, w_enc, w_attn);

    const int SMEM_MEGA = (100 * 68 + 100 * 68 + 64 * 68 + 32 * 66 * 2) * 4;
    cudaFuncSetAttribute(mega_kernel,
                         cudaFuncAttributeMaxDynamicSharedMemorySize, SMEM_MEGA);
    mega_kernel<<<NCTA, 256, SMEM_MEGA>>>(
        decoded, b_val, b_dec, contexts, b_enc,
        w_agg, b_agg, b_attn, out);
}